// round 2
// baseline (speedup 1.0000x reference)
#include <cuda_runtime.h>

#define NV 5
#define NS 4
#define CC 32
#define HH 128
#define WW 160
#define DDEP 48
#define HWSZ (HH*WW)          // 20480
#define DHWSZ (DDEP*HWSZ)     // 983040

// conv tiling
#define HT 2                  // output h rows per block
#define HS 4                  // staged h rows (HT + 2 halo)
#define DT 8                  // output depths per block
#define DS 10                 // staged depths (DT + 2 halo)
#define DP 12                 // padded depth stride (16B aligned: 12 floats = 48B)
#define WP 162                // staged w (160 + 2 halo)
#define CONV_THREADS 320

// ---------------- scratch (static device globals; no runtime allocation) ----
__device__ float g_rot[NS][9];
__device__ float g_trans[NS][3];
__device__ float g_feaT[NV*HWSZ*CC];            // (view, h, w, c)  13.1 MB
__device__ float g_var[(size_t)CC*DHWSZ];       // planar (c, d,h,w) 125.8 MB
__device__ float g_cost[DHWSZ];                 // (d,h,w) 3.9 MB

// ---------------- packed f32x2 helpers --------------------------------------
__device__ __forceinline__ unsigned long long pk2(float lo, float hi) {
    unsigned long long p;
    asm("mov.b64 %0, {%1, %2};" : "=l"(p) : "f"(lo), "f"(hi));
    return p;
}
__device__ __forceinline__ unsigned long long fma2(unsigned long long a,
                                                   unsigned long long b,
                                                   unsigned long long c) {
    unsigned long long d;
    asm("fma.rn.f32x2 %0, %1, %2, %3;" : "=l"(d) : "l"(a), "l"(b), "l"(c));
    return d;
}
__device__ __forceinline__ void upk2(unsigned long long p, float& lo, float& hi) {
    asm("mov.b64 {%0, %1}, %2;" : "=f"(lo), "=f"(hi) : "l"(p));
}

// ---------------- kernel 0: projection setup (1 thread) ---------------------
__global__ void k_setup(const float* __restrict__ pm) {
    if (threadIdx.x != 0 || blockIdx.x != 0) return;
    double fused[NV][16];
    for (int n = 0; n < NV; n++) {
        const float* p0 = pm + n * 32;
        const float* p1 = p0 + 16;
        for (int i = 0; i < 16; i++) fused[n][i] = (double)p0[i];
        for (int i = 0; i < 3; i++)
            for (int j = 0; j < 4; j++) {
                double s = 0.0;
                for (int k = 0; k < 3; k++) s += (double)p1[i*4+k] * (double)p0[k*4+j];
                fused[n][i*4+j] = s;
            }
    }
    double a[4][8];
    for (int i = 0; i < 4; i++)
        for (int j = 0; j < 4; j++) {
            a[i][j]   = fused[0][i*4+j];
            a[i][j+4] = (i == j) ? 1.0 : 0.0;
        }
    for (int col = 0; col < 4; col++) {
        int piv = col;
        for (int r = col + 1; r < 4; r++)
            if (fabs(a[r][col]) > fabs(a[piv][col])) piv = r;
        if (piv != col)
            for (int j = 0; j < 8; j++) { double t = a[col][j]; a[col][j] = a[piv][j]; a[piv][j] = t; }
        double d = a[col][col];
        for (int j = 0; j < 8; j++) a[col][j] /= d;
        for (int r = 0; r < 4; r++) {
            if (r == col) continue;
            double f = a[r][col];
            for (int j = 0; j < 8; j++) a[r][j] -= f * a[col][j];
        }
    }
    double inv[16];
    for (int i = 0; i < 4; i++)
        for (int j = 0; j < 4; j++) inv[i*4+j] = a[i][j+4];

    for (int v = 1; v < NV; v++) {
        double P[16];
        for (int i = 0; i < 4; i++)
            for (int j = 0; j < 4; j++) {
                double s = 0.0;
                for (int k = 0; k < 4; k++) s += fused[v][i*4+k] * inv[k*4+j];
                P[i*4+j] = s;
            }
        for (int i = 0; i < 3; i++)
            for (int j = 0; j < 3; j++) g_rot[v-1][i*3+j] = (float)P[i*4+j];
        for (int i = 0; i < 3; i++) g_trans[v-1][i] = (float)P[i*4+3];
    }
}

// ---------------- kernel 1: transpose features (N,C,H,W) -> (N,HW,C) --------
__global__ void k_transpose(const float* __restrict__ f) {
    __shared__ float tile[32][33];
    int n  = blockIdx.z;
    int p0 = blockIdx.x * 32;
    int tx = threadIdx.x, ty = threadIdx.y;
    tile[ty][tx] = f[((size_t)(n*CC + ty))*HWSZ + p0 + tx];
    __syncthreads();
    g_feaT[((size_t)(n*HWSZ + p0 + ty))*CC + tx] = tile[tx][ty];
}

// ---------------- kernel 2: warp + variance (planar output) -----------------
__global__ void __launch_bounds__(128) k_var(const float* __restrict__ dv) {
    __shared__ int4   s_idx[4][4][32];
    __shared__ float4 s_wt [4][4][32];
    __shared__ int    s_hw [4][32];
    __shared__ float  s_var[128*33];

    const int tid  = threadIdx.x;
    const int warp = tid >> 5;
    const int lane = tid & 31;
    const int gblock = blockIdx.x * 128;

    {
        int g  = gblock + tid;
        int d  = g / HWSZ;
        int hw = g - d * HWSZ;
        int h  = hw / WW;
        int w  = hw - h * WW;
        float fx = (float)w, fy = (float)h;
        float depth = __ldg(dv + d);
        #pragma unroll
        for (int v = 0; v < NS; v++) {
            float r0 = g_rot[v][0], r1 = g_rot[v][1], r2 = g_rot[v][2];
            float r3 = g_rot[v][3], r4 = g_rot[v][4], r5 = g_rot[v][5];
            float r6 = g_rot[v][6], r7 = g_rot[v][7], r8 = g_rot[v][8];
            float t0 = g_trans[v][0], t1 = g_trans[v][1], t2 = g_trans[v][2];
            float rx = r0*fx + r1*fy + r2;
            float ry = r3*fx + r4*fy + r5;
            float rz = r6*fx + r7*fy + r8;
            float X = rx*depth + t0;
            float Y = ry*depth + t1;
            float Z = rz*depth + t2;
            float px = X / Z;
            float py = Y / Z;
            float x0 = floorf(px), y0 = floorf(py);
            float x1 = x0 + 1.0f,  y1 = y0 + 1.0f;
            float wx1 = px - x0, wx0 = 1.0f - wx1;
            float wy1 = py - y0, wy0 = 1.0f - wy1;
            bool vx0 = (x0 >= 0.0f) && (x0 <= (float)(WW-1));
            bool vx1 = (x1 >= 0.0f) && (x1 <= (float)(WW-1));
            bool vy0 = (y0 >= 0.0f) && (y0 <= (float)(HH-1));
            bool vy1 = (y1 >= 0.0f) && (y1 <= (float)(HH-1));
            int cx0 = (int)fminf(fmaxf(x0, 0.0f), (float)(WW-1));
            int cx1 = (int)fminf(fmaxf(x1, 0.0f), (float)(WW-1));
            int cy0 = (int)fminf(fmaxf(y0, 0.0f), (float)(HH-1));
            int cy1 = (int)fminf(fmaxf(y1, 0.0f), (float)(HH-1));
            int4 id;
            id.x = cy0*WW + cx0;
            id.y = cy0*WW + cx1;
            id.z = cy1*WW + cx0;
            id.w = cy1*WW + cx1;
            float4 wt;
            wt.x = wx0*wy0 * ((vx0 && vy0) ? 1.0f : 0.0f);
            wt.y = wx1*wy0 * ((vx1 && vy0) ? 1.0f : 0.0f);
            wt.z = wx0*wy1 * ((vx0 && vy1) ? 1.0f : 0.0f);
            wt.w = wx1*wy1 * ((vx1 && vy1) ? 1.0f : 0.0f);
            s_idx[warp][v][lane] = id;
            s_wt [warp][v][lane] = wt;
        }
        s_hw[warp][lane] = hw;
    }
    __syncwarp();

    const int cg = lane & 7;
    const int q  = lane >> 3;
    const float4* fT = (const float4*)g_feaT;
    const float invN = 1.0f / (float)NV;

    #pragma unroll
    for (int it = 0; it < 8; it++) {
        int pt  = it*4 + q;
        int hw2 = s_hw[warp][pt];
        float4 ref = fT[hw2*8 + cg];
        float sx = ref.x, sy = ref.y, sz = ref.z, sw = ref.w;
        float qx = ref.x*ref.x, qy = ref.y*ref.y, qz = ref.z*ref.z, qw = ref.w*ref.w;
        #pragma unroll
        for (int v = 0; v < NS; v++) {
            int4   id = s_idx[warp][v][pt];
            float4 wt = s_wt [warp][v][pt];
            const float4* fv = fT + (size_t)(v+1)*HWSZ*8;
            float4 c00 = fv[id.x*8 + cg];
            float4 c01 = fv[id.y*8 + cg];
            float4 c10 = fv[id.z*8 + cg];
            float4 c11 = fv[id.w*8 + cg];
            float vx = wt.x*c00.x + wt.y*c01.x + wt.z*c10.x + wt.w*c11.x;
            float vy = wt.x*c00.y + wt.y*c01.y + wt.z*c10.y + wt.w*c11.y;
            float vz = wt.x*c00.z + wt.y*c01.z + wt.z*c10.z + wt.w*c11.z;
            float vw = wt.x*c00.w + wt.y*c01.w + wt.z*c10.w + wt.w*c11.w;
            sx += vx; sy += vy; sz += vz; sw += vw;
            qx += vx*vx; qy += vy*vy; qz += vz*vz; qw += vw*vw;
        }
        float mx = sx*invN, my = sy*invN, mz = sz*invN, mw = sw*invN;
        float vrx = qx*invN - mx*mx;
        float vry = qy*invN - my*my;
        float vrz = qz*invN - mz*mz;
        float vrw = qw*invN - mw*mw;
        int sbase = (warp*32 + pt)*33 + cg*4;
        s_var[sbase+0] = vrx;
        s_var[sbase+1] = vry;
        s_var[sbase+2] = vrz;
        s_var[sbase+3] = vrw;
    }
    __syncthreads();

    int gg = gblock + tid;
    #pragma unroll
    for (int c = 0; c < CC; c++)
        g_var[(size_t)c*DHWSZ + gg] = s_var[tid*33 + c];
}

// ---------------- kernel 3: 3x3x3 conv, smem-tiled + packed f32x2 -----------
__global__ void __launch_bounds__(CONV_THREADS, 2) k_conv(const float* __restrict__ wgt) {
    __shared__ float slab[HS][WP][DP];              // 31.1 KB
    __shared__ unsigned long long wpk[CC*27];       // 6.9 KB  ({k,k} pairs)

    const int tid = threadIdx.x;
    const int h0  = blockIdx.x * HT;
    const int d0  = blockIdx.y * DT;
    const int w   = tid % WW;
    const int hl  = tid / WW;                       // 0..HT-1

    // prepack broadcast weight pairs (once)
    for (int i = tid; i < CC*27; i += CONV_THREADS) {
        float k = __ldg(wgt + i);
        wpk[i] = pk2(k, k);
    }
    // zero w-halo columns (never overwritten afterwards)
    for (int i = tid; i < HS*DS; i += CONV_THREADS) {
        int shy = i / DS, sdd = i % DS;
        slab[shy][0][sdd]    = 0.0f;
        slab[shy][WP-1][sdd] = 0.0f;
    }

    unsigned long long A0 = 0ull, A1 = 0ull, A2 = 0ull, A3 = 0ull;

    #pragma unroll 1
    for (int c = 0; c < CC; c++) {
        __syncthreads();   // prev compute done (and first-iter: halo/wpk visible)

        // ---- cooperative slab load: 40 rows (sdd,shy) x 160 w, float4 ----
        const float* __restrict__ vc = g_var + (size_t)c * DHWSZ;
        #pragma unroll
        for (int r = 0; r < 5; r++) {
            int idx = r*CONV_THREADS + tid;         // 0..1599
            int row = idx / 40;                      // 0..39
            int w4  = (idx % 40) * 4;
            int shy = row / DS;                      // 0..3
            int sdd = row - shy*DS;                  // 0..9
            int dd  = d0 - 1 + sdd;
            int hy  = h0 - 1 + shy;
            float4 v = make_float4(0.f, 0.f, 0.f, 0.f);
            if (dd >= 0 && dd < DDEP && hy >= 0 && hy < HH)
                v = *(const float4*)(vc + (size_t)dd*HWSZ + hy*WW + w4);
            float* dst = &slab[shy][w4 + 1][sdd];
            dst[0]    = v.x;
            dst[DP]   = v.y;
            dst[2*DP] = v.z;
            dst[3*DP] = v.w;
        }
        __syncthreads();

        // ---- compute: 9 spatial taps, packed depth pairs ----
        const unsigned long long* wc = wpk + c*27;
        #pragma unroll
        for (int dy = 0; dy < 3; dy++) {
            #pragma unroll
            for (int dx = 0; dx < 3; dx++) {
                const float* col = &slab[hl + dy][w + dx][0];
                float4 va = *(const float4*)(col);       // v[0..3]
                float4 vb = *(const float4*)(col + 4);   // v[4..7]
                float2 vt = *(const float2*)(col + 8);   // v[8..9]
                unsigned long long e0 = pk2(va.x, va.y); // (0,1)
                unsigned long long e1 = pk2(va.z, va.w); // (2,3)
                unsigned long long e2 = pk2(vb.x, vb.y); // (4,5)
                unsigned long long e3 = pk2(vb.z, vb.w); // (6,7)
                unsigned long long o0 = pk2(va.y, va.z); // (1,2)
                unsigned long long o1 = pk2(va.w, vb.x); // (3,4)
                unsigned long long o2 = pk2(vb.y, vb.z); // (5,6)
                unsigned long long o3 = pk2(vb.w, vt.x); // (7,8)
                unsigned long long t0 = pk2(vt.x, vt.y); // (8,9)
                unsigned long long k0 = wc[(0*3 + dy)*3 + dx];
                unsigned long long k1 = wc[(1*3 + dy)*3 + dx];
                unsigned long long k2 = wc[(2*3 + dy)*3 + dx];
                A0 = fma2(e0, k0, A0); A1 = fma2(e1, k0, A1);
                A2 = fma2(e2, k0, A2); A3 = fma2(e3, k0, A3);
                A0 = fma2(o0, k1, A0); A1 = fma2(o1, k1, A1);
                A2 = fma2(o2, k1, A2); A3 = fma2(o3, k1, A3);
                A0 = fma2(e1, k2, A0); A1 = fma2(e2, k2, A1);
                A2 = fma2(e3, k2, A2); A3 = fma2(t0, k2, A3);
            }
        }
    }

    // ---- store 8 depth outputs ----
    float r0, r1, r2, r3, r4, r5, r6, r7;
    upk2(A0, r0, r1); upk2(A1, r2, r3); upk2(A2, r4, r5); upk2(A3, r6, r7);
    const int ob = (h0 + hl)*WW + w;
    g_cost[(size_t)(d0+0)*HWSZ + ob] = r0;
    g_cost[(size_t)(d0+1)*HWSZ + ob] = r1;
    g_cost[(size_t)(d0+2)*HWSZ + ob] = r2;
    g_cost[(size_t)(d0+3)*HWSZ + ob] = r3;
    g_cost[(size_t)(d0+4)*HWSZ + ob] = r4;
    g_cost[(size_t)(d0+5)*HWSZ + ob] = r5;
    g_cost[(size_t)(d0+6)*HWSZ + ob] = r6;
    g_cost[(size_t)(d0+7)*HWSZ + ob] = r7;
}

// ---------------- kernel 4: softmax / depth / confidence --------------------
__global__ void __launch_bounds__(256) k_post(const float* __restrict__ dv,
                                              float* __restrict__ out) {
    int pix = blockIdx.x * 256 + threadIdx.x;
    float p[DDEP];
    float mx = -1e30f;
    #pragma unroll
    for (int d = 0; d < DDEP; d++) {
        p[d] = g_cost[(size_t)d*HWSZ + pix];
        mx = fmaxf(mx, p[d]);
    }
    float s = 0.0f;
    #pragma unroll
    for (int d = 0; d < DDEP; d++) { p[d] = expf(p[d] - mx); s += p[d]; }
    float inv = 1.0f / s;
    float depth = 0.0f, didx = 0.0f;
    #pragma unroll
    for (int d = 0; d < DDEP; d++) {
        float pr = p[d] * inv;
        p[d] = pr;
        depth += pr * __ldg(dv + d);
        didx  += pr * (float)d;
    }
    int di = (int)didx;
    di = min(max(di, 0), DDEP - 1);
    float conf = 0.0f;
    #pragma unroll
    for (int d = 0; d < DDEP; d++) {
        bool inwin = (d >= di - 1) && (d <= di + 2);
        conf += inwin ? p[d] : 0.0f;
    }
    out[pix]        = depth;
    out[HWSZ + pix] = conf;
}

// ---------------- launcher ---------------------------------------------------
extern "C" void kernel_launch(void* const* d_in, const int* in_sizes, int n_in,
                              void* d_out, int out_size) {
    const float* features = nullptr;
    const float* pm       = nullptr;
    const float* dv       = nullptr;
    const float* wgt      = nullptr;
    for (int i = 0; i < n_in; i++) {
        switch (in_sizes[i]) {
            case NV*CC*HWSZ: features = (const float*)d_in[i]; break;
            case 160:        pm       = (const float*)d_in[i]; break;
            case 48:         dv       = (const float*)d_in[i]; break;
            case 864:        wgt      = (const float*)d_in[i]; break;
            default: break;
        }
    }
    if (!features) features = (const float*)d_in[0];
    if (!pm)       pm       = (const float*)d_in[1];
    if (!dv)       dv       = (const float*)d_in[2];
    if (!wgt)      wgt      = (const float*)d_in[3];
    float* out = (float*)d_out;

    k_setup<<<1, 32>>>(pm);
    k_transpose<<<dim3(HWSZ/32, 1, NV), dim3(32, 32)>>>(features);
    k_var<<<DHWSZ/128, 128>>>(dv);
    k_conv<<<dim3(HH/HT, DDEP/DT), CONV_THREADS>>>(wgt);
    k_post<<<HWSZ/256, 256>>>(dv, out);
}

// round 3
// speedup vs baseline: 1.2612x; 1.2612x over previous
#include <cuda_runtime.h>

#define NV 5
#define NS 4
#define CC 32
#define HH 128
#define WW 160
#define DDEP 48
#define HWSZ (HH*WW)          // 20480
#define DHWSZ (DDEP*HWSZ)     // 983040

// conv tiling: block = 4 h-rows x full W x 8 depths; thread = 4w x 8d
#define HT 4
#define HS 6                  // HT + 2 halo
#define DT 8
#define DS 10                 // DT + 2 halo
#define WP 168                // 4 zero + 160 data + 4 zero  (s = w + 4)
#define CONV_THREADS 160      // 40 w-groups x 4 h

// ---------------- scratch (static device globals; no runtime allocation) ----
__device__ float g_rot[NS][9];
__device__ float g_trans[NS][3];
__device__ float g_feaT[NV*HWSZ*CC];            // (view, h, w, c)  13.1 MB
__device__ float g_var[(size_t)CC*DHWSZ];       // planar (c, d,h,w) 125.8 MB
__device__ float g_cost[DHWSZ];                 // (d,h,w) 3.9 MB

// ---------------- packed f32x2 helpers --------------------------------------
__device__ __forceinline__ unsigned long long pk2(float lo, float hi) {
    unsigned long long p;
    asm("mov.b64 %0, {%1, %2};" : "=l"(p) : "f"(lo), "f"(hi));
    return p;
}
__device__ __forceinline__ unsigned long long fma2(unsigned long long a,
                                                   unsigned long long b,
                                                   unsigned long long c) {
    unsigned long long d;
    asm("fma.rn.f32x2 %0, %1, %2, %3;" : "=l"(d) : "l"(a), "l"(b), "l"(c));
    return d;
}
__device__ __forceinline__ void upk2(unsigned long long p, float& lo, float& hi) {
    asm("mov.b64 {%0, %1}, %2;" : "=f"(lo), "=f"(hi) : "l"(p));
}

// ---------------- kernel 0: projection setup (1 thread) ---------------------
__global__ void k_setup(const float* __restrict__ pm) {
    if (threadIdx.x != 0 || blockIdx.x != 0) return;
    double fused[NV][16];
    for (int n = 0; n < NV; n++) {
        const float* p0 = pm + n * 32;
        const float* p1 = p0 + 16;
        for (int i = 0; i < 16; i++) fused[n][i] = (double)p0[i];
        for (int i = 0; i < 3; i++)
            for (int j = 0; j < 4; j++) {
                double s = 0.0;
                for (int k = 0; k < 3; k++) s += (double)p1[i*4+k] * (double)p0[k*4+j];
                fused[n][i*4+j] = s;
            }
    }
    double a[4][8];
    for (int i = 0; i < 4; i++)
        for (int j = 0; j < 4; j++) {
            a[i][j]   = fused[0][i*4+j];
            a[i][j+4] = (i == j) ? 1.0 : 0.0;
        }
    for (int col = 0; col < 4; col++) {
        int piv = col;
        for (int r = col + 1; r < 4; r++)
            if (fabs(a[r][col]) > fabs(a[piv][col])) piv = r;
        if (piv != col)
            for (int j = 0; j < 8; j++) { double t = a[col][j]; a[col][j] = a[piv][j]; a[piv][j] = t; }
        double d = a[col][col];
        for (int j = 0; j < 8; j++) a[col][j] /= d;
        for (int r = 0; r < 4; r++) {
            if (r == col) continue;
            double f = a[r][col];
            for (int j = 0; j < 8; j++) a[r][j] -= f * a[col][j];
        }
    }
    double inv[16];
    for (int i = 0; i < 4; i++)
        for (int j = 0; j < 4; j++) inv[i*4+j] = a[i][j+4];

    for (int v = 1; v < NV; v++) {
        double P[16];
        for (int i = 0; i < 4; i++)
            for (int j = 0; j < 4; j++) {
                double s = 0.0;
                for (int k = 0; k < 4; k++) s += fused[v][i*4+k] * inv[k*4+j];
                P[i*4+j] = s;
            }
        for (int i = 0; i < 3; i++)
            for (int j = 0; j < 3; j++) g_rot[v-1][i*3+j] = (float)P[i*4+j];
        for (int i = 0; i < 3; i++) g_trans[v-1][i] = (float)P[i*4+3];
    }
}

// ---------------- kernel 1: transpose features (N,C,H,W) -> (N,HW,C) --------
__global__ void k_transpose(const float* __restrict__ f) {
    __shared__ float tile[32][33];
    int n  = blockIdx.z;
    int p0 = blockIdx.x * 32;
    int tx = threadIdx.x, ty = threadIdx.y;
    tile[ty][tx] = f[((size_t)(n*CC + ty))*HWSZ + p0 + tx];
    __syncthreads();
    g_feaT[((size_t)(n*HWSZ + p0 + ty))*CC + tx] = tile[tx][ty];
}

// ---------------- kernel 2: warp + variance (planar output) -----------------
__global__ void __launch_bounds__(128) k_var(const float* __restrict__ dv) {
    __shared__ int4   s_idx[4][4][32];
    __shared__ float4 s_wt [4][4][32];
    __shared__ int    s_hw [4][32];
    __shared__ float  s_var[128*33];

    const int tid  = threadIdx.x;
    const int warp = tid >> 5;
    const int lane = tid & 31;
    const int gblock = blockIdx.x * 128;

    {
        int g  = gblock + tid;
        int d  = g / HWSZ;
        int hw = g - d * HWSZ;
        int h  = hw / WW;
        int w  = hw - h * WW;
        float fx = (float)w, fy = (float)h;
        float depth = __ldg(dv + d);
        #pragma unroll
        for (int v = 0; v < NS; v++) {
            float r0 = g_rot[v][0], r1 = g_rot[v][1], r2 = g_rot[v][2];
            float r3 = g_rot[v][3], r4 = g_rot[v][4], r5 = g_rot[v][5];
            float r6 = g_rot[v][6], r7 = g_rot[v][7], r8 = g_rot[v][8];
            float t0 = g_trans[v][0], t1 = g_trans[v][1], t2 = g_trans[v][2];
            float rx = r0*fx + r1*fy + r2;
            float ry = r3*fx + r4*fy + r5;
            float rz = r6*fx + r7*fy + r8;
            float X = rx*depth + t0;
            float Y = ry*depth + t1;
            float Z = rz*depth + t2;
            float px = X / Z;
            float py = Y / Z;
            float x0 = floorf(px), y0 = floorf(py);
            float x1 = x0 + 1.0f,  y1 = y0 + 1.0f;
            float wx1 = px - x0, wx0 = 1.0f - wx1;
            float wy1 = py - y0, wy0 = 1.0f - wy1;
            bool vx0 = (x0 >= 0.0f) && (x0 <= (float)(WW-1));
            bool vx1 = (x1 >= 0.0f) && (x1 <= (float)(WW-1));
            bool vy0 = (y0 >= 0.0f) && (y0 <= (float)(HH-1));
            bool vy1 = (y1 >= 0.0f) && (y1 <= (float)(HH-1));
            int cx0 = (int)fminf(fmaxf(x0, 0.0f), (float)(WW-1));
            int cx1 = (int)fminf(fmaxf(x1, 0.0f), (float)(WW-1));
            int cy0 = (int)fminf(fmaxf(y0, 0.0f), (float)(HH-1));
            int cy1 = (int)fminf(fmaxf(y1, 0.0f), (float)(HH-1));
            int4 id;
            id.x = cy0*WW + cx0;
            id.y = cy0*WW + cx1;
            id.z = cy1*WW + cx0;
            id.w = cy1*WW + cx1;
            float4 wt;
            wt.x = wx0*wy0 * ((vx0 && vy0) ? 1.0f : 0.0f);
            wt.y = wx1*wy0 * ((vx1 && vy0) ? 1.0f : 0.0f);
            wt.z = wx0*wy1 * ((vx0 && vy1) ? 1.0f : 0.0f);
            wt.w = wx1*wy1 * ((vx1 && vy1) ? 1.0f : 0.0f);
            s_idx[warp][v][lane] = id;
            s_wt [warp][v][lane] = wt;
        }
        s_hw[warp][lane] = hw;
    }
    __syncwarp();

    const int cg = lane & 7;
    const int q  = lane >> 3;
    const float4* fT = (const float4*)g_feaT;
    const float invN = 1.0f / (float)NV;

    #pragma unroll
    for (int it = 0; it < 8; it++) {
        int pt  = it*4 + q;
        int hw2 = s_hw[warp][pt];
        float4 ref = fT[hw2*8 + cg];
        float sx = ref.x, sy = ref.y, sz = ref.z, sw = ref.w;
        float qx = ref.x*ref.x, qy = ref.y*ref.y, qz = ref.z*ref.z, qw = ref.w*ref.w;
        #pragma unroll
        for (int v = 0; v < NS; v++) {
            int4   id = s_idx[warp][v][pt];
            float4 wt = s_wt [warp][v][pt];
            const float4* fv = fT + (size_t)(v+1)*HWSZ*8;
            float4 c00 = fv[id.x*8 + cg];
            float4 c01 = fv[id.y*8 + cg];
            float4 c10 = fv[id.z*8 + cg];
            float4 c11 = fv[id.w*8 + cg];
            float vx = wt.x*c00.x + wt.y*c01.x + wt.z*c10.x + wt.w*c11.x;
            float vy = wt.x*c00.y + wt.y*c01.y + wt.z*c10.y + wt.w*c11.y;
            float vz = wt.x*c00.z + wt.y*c01.z + wt.z*c10.z + wt.w*c11.z;
            float vw = wt.x*c00.w + wt.y*c01.w + wt.z*c10.w + wt.w*c11.w;
            sx += vx; sy += vy; sz += vz; sw += vw;
            qx += vx*vx; qy += vy*vy; qz += vz*vz; qw += vw*vw;
        }
        float mx = sx*invN, my = sy*invN, mz = sz*invN, mw = sw*invN;
        float vrx = qx*invN - mx*mx;
        float vry = qy*invN - my*my;
        float vrz = qz*invN - mz*mz;
        float vrw = qw*invN - mw*mw;
        int sbase = (warp*32 + pt)*33 + cg*4;
        s_var[sbase+0] = vrx;
        s_var[sbase+1] = vry;
        s_var[sbase+2] = vrz;
        s_var[sbase+3] = vrw;
    }
    __syncthreads();

    int gg = gblock + tid;
    #pragma unroll
    for (int c = 0; c < CC; c++)
        g_var[(size_t)c*DHWSZ + gg] = s_var[tid*33 + c];
}

// ---------------- kernel 3: 3x3x3 conv, w-contiguous slab + f32x2 over w ----
__global__ void __launch_bounds__(CONV_THREADS) k_conv(const float* __restrict__ wgt) {
    __shared__ float slab[HS][DS][WP];              // 40.3 KB, w-contiguous
    __shared__ unsigned long long wpk[CC*27];       // 6.9 KB packed {k,k}

    const int tid = threadIdx.x;
    const int h0  = blockIdx.x * HT;
    const int d0  = blockIdx.y * DT;
    const int wg  = tid % 40;
    const int hl  = tid / 40;                       // 0..HT-1
    const int w0  = wg * 4;

    // prepack weight pairs
    for (int i = tid; i < CC*27; i += CONV_THREADS) {
        float k = __ldg(wgt + i);
        wpk[i] = pk2(k, k);
    }
    // zero halo columns (s=0..3 and s=164..167); only s=3 and s=164 are read
    for (int i = tid; i < HS*DS; i += CONV_THREADS) {
        int shy = i / DS, sdd = i % DS;
        float* row = &slab[shy][sdd][0];
        row[0] = 0.f; row[1] = 0.f; row[2] = 0.f; row[3] = 0.f;
        row[164] = 0.f; row[165] = 0.f; row[166] = 0.f; row[167] = 0.f;
    }

    // accumulators: A[od][0] = outputs (w0, w0+1), A[od][1] = (w0+2, w0+3)
    unsigned long long A[DT][2];
    #pragma unroll
    for (int od = 0; od < DT; od++) { A[od][0] = 0ull; A[od][1] = 0ull; }

    #pragma unroll 1
    for (int c = 0; c < CC; c++) {
        __syncthreads();   // previous compute done / halo visible

        // ---- cooperative slab load: 60 rows x 160 w, float4, coalesced ----
        const float* __restrict__ vc = g_var + (size_t)c * DHWSZ;
        #pragma unroll
        for (int r = 0; r < 15; r++) {
            int idx = r*CONV_THREADS + tid;          // 0..2399
            int row = idx / 40;                      // 0..59
            int w4  = (idx % 40) * 4;
            int shy = row / DS;                      // 0..5
            int sdd = row - shy*DS;                  // 0..9
            int dd  = d0 - 1 + sdd;
            int hy  = h0 - 1 + shy;
            float4 v = make_float4(0.f, 0.f, 0.f, 0.f);
            if (dd >= 0 && dd < DDEP && hy >= 0 && hy < HH)
                v = *(const float4*)(vc + (size_t)dd*HWSZ + hy*WW + w4);
            *(float4*)&slab[shy][sdd][w4 + 4] = v;   // always store (zero if OOB)
        }
        __syncthreads();

        // ---- compute ----
        const unsigned long long* wc = wpk + c*27;   // [(dz*3+dy)*3+dx]
        #pragma unroll
        for (int dy = 0; dy < 3; dy++) {
            // hoist this dy's 9 weight pairs
            unsigned long long k00 = wc[(0*3+dy)*3+0], k01 = wc[(0*3+dy)*3+1], k02 = wc[(0*3+dy)*3+2];
            unsigned long long k10 = wc[(1*3+dy)*3+0], k11 = wc[(1*3+dy)*3+1], k12 = wc[(1*3+dy)*3+2];
            unsigned long long k20 = wc[(2*3+dy)*3+0], k21 = wc[(2*3+dy)*3+1], k22 = wc[(2*3+dy)*3+2];
            const float* hrow = &slab[hl + dy][0][0];
            #pragma unroll
            for (int sdd = 0; sdd < DS; sdd++) {
                const float* col = hrow + sdd*WP;
                float4 a = *(const float4*)(col + w0 + 4);   // w0..w0+3
                float2 l = *(const float2*)(col + w0 + 2);   // w0-2, w0-1
                float2 rr = *(const float2*)(col + w0 + 8);  // w0+4, w0+5
                unsigned long long P0 = pk2(l.y,  a.x);      // (v-1, v0)
                unsigned long long P1 = pk2(a.x,  a.y);      // (v0, v1)
                unsigned long long P2 = pk2(a.y,  a.z);      // (v1, v2)
                unsigned long long P3 = pk2(a.z,  a.w);      // (v2, v3)
                unsigned long long P4 = pk2(a.w,  rr.x);     // (v3, v4)
                #pragma unroll
                for (int dz = 0; dz < 3; dz++) {
                    int od = sdd - dz;
                    if (od < 0 || od >= DT) continue;        // resolved at compile time
                    unsigned long long q0 = (dz==0) ? k00 : (dz==1) ? k10 : k20;
                    unsigned long long q1 = (dz==0) ? k01 : (dz==1) ? k11 : k21;
                    unsigned long long q2 = (dz==0) ? k02 : (dz==1) ? k12 : k22;
                    A[od][0] = fma2(P0, q0, A[od][0]);
                    A[od][0] = fma2(P1, q1, A[od][0]);
                    A[od][0] = fma2(P2, q2, A[od][0]);
                    A[od][1] = fma2(P2, q0, A[od][1]);
                    A[od][1] = fma2(P3, q1, A[od][1]);
                    A[od][1] = fma2(P4, q2, A[od][1]);
                }
            }
        }
    }

    // ---- store 4w x 8d outputs ----
    const int ob = (h0 + hl)*WW + w0;
    #pragma unroll
    for (int od = 0; od < DT; od++) {
        float o0, o1, o2, o3;
        upk2(A[od][0], o0, o1);
        upk2(A[od][1], o2, o3);
        float4 v = make_float4(o0, o1, o2, o3);
        *(float4*)(g_cost + (size_t)(d0 + od)*HWSZ + ob) = v;
    }
}

// ---------------- kernel 4: softmax / depth / confidence --------------------
__global__ void __launch_bounds__(256) k_post(const float* __restrict__ dv,
                                              float* __restrict__ out) {
    int pix = blockIdx.x * 256 + threadIdx.x;
    float p[DDEP];
    float mx = -1e30f;
    #pragma unroll
    for (int d = 0; d < DDEP; d++) {
        p[d] = g_cost[(size_t)d*HWSZ + pix];
        mx = fmaxf(mx, p[d]);
    }
    float s = 0.0f;
    #pragma unroll
    for (int d = 0; d < DDEP; d++) { p[d] = expf(p[d] - mx); s += p[d]; }
    float inv = 1.0f / s;
    float depth = 0.0f, didx = 0.0f;
    #pragma unroll
    for (int d = 0; d < DDEP; d++) {
        float pr = p[d] * inv;
        p[d] = pr;
        depth += pr * __ldg(dv + d);
        didx  += pr * (float)d;
    }
    int di = (int)didx;
    di = min(max(di, 0), DDEP - 1);
    float conf = 0.0f;
    #pragma unroll
    for (int d = 0; d < DDEP; d++) {
        bool inwin = (d >= di - 1) && (d <= di + 2);
        conf += inwin ? p[d] : 0.0f;
    }
    out[pix]        = depth;
    out[HWSZ + pix] = conf;
}

// ---------------- launcher ---------------------------------------------------
extern "C" void kernel_launch(void* const* d_in, const int* in_sizes, int n_in,
                              void* d_out, int out_size) {
    const float* features = nullptr;
    const float* pm       = nullptr;
    const float* dv       = nullptr;
    const float* wgt      = nullptr;
    for (int i = 0; i < n_in; i++) {
        switch (in_sizes[i]) {
            case NV*CC*HWSZ: features = (const float*)d_in[i]; break;
            case 160:        pm       = (const float*)d_in[i]; break;
            case 48:         dv       = (const float*)d_in[i]; break;
            case 864:        wgt      = (const float*)d_in[i]; break;
            default: break;
        }
    }
    if (!features) features = (const float*)d_in[0];
    if (!pm)       pm       = (const float*)d_in[1];
    if (!dv)       dv       = (const float*)d_in[2];
    if (!wgt)      wgt      = (const float*)d_in[3];
    float* out = (float*)d_out;

    k_setup<<<1, 32>>>(pm);
    k_transpose<<<dim3(HWSZ/32, 1, NV), dim3(32, 32)>>>(features);
    k_var<<<DHWSZ/128, 128>>>(dv);
    k_conv<<<dim3(HH/HT, DDEP/DT), CONV_THREADS>>>(wgt);
    k_post<<<HWSZ/256, 256>>>(dv, out);
}

// round 4
// speedup vs baseline: 1.5445x; 1.2247x over previous
#include <cuda_runtime.h>

#define NV 5
#define NS 4
#define CC 32
#define HH 128
#define WW 160
#define DDEP 48
#define HWSZ (HH*WW)          // 20480
#define DHWSZ (DDEP*HWSZ)     // 983040

// conv tiling: block = 4 h-rows x full W x 8 depths x 16 channels
#define HT 4
#define HS 6                  // HT + 2 halo
#define DT 8
#define DS 10                 // DT + 2 halo
#define WP 168                // 4 zero + 160 data + 4 zero  (s = w + 4)
#define CONV_THREADS 160      // 40 w-groups x 4 h
#define CSPLIT 2
#define CPB (CC/CSPLIT)       // 16 channels per block

// ---------------- scratch (static device globals; no runtime allocation) ----
__device__ float g_rot[NS][9];
__device__ float g_trans[NS][3];
__device__ float g_feaT[NV*HWSZ*CC];            // (view, h, w, c)  13.1 MB
__device__ float g_var[(size_t)CC*DHWSZ];       // planar (c, d,h,w) 125.8 MB
__device__ float g_cost[DHWSZ];                 // partial (channels 0..15)
__device__ float g_cost2[DHWSZ];                // partial (channels 16..31)

// ---------------- packed f32x2 helpers --------------------------------------
__device__ __forceinline__ unsigned long long pk2(float lo, float hi) {
    unsigned long long p;
    asm("mov.b64 %0, {%1, %2};" : "=l"(p) : "f"(lo), "f"(hi));
    return p;
}
__device__ __forceinline__ unsigned long long fma2(unsigned long long a,
                                                   unsigned long long b,
                                                   unsigned long long c) {
    unsigned long long d;
    asm("fma.rn.f32x2 %0, %1, %2, %3;" : "=l"(d) : "l"(a), "l"(b), "l"(c));
    return d;
}
__device__ __forceinline__ void upk2(unsigned long long p, float& lo, float& hi) {
    asm("mov.b64 {%0, %1}, %2;" : "=f"(lo), "=f"(hi) : "l"(p));
}

// ---------------- kernel 0: projection setup (1 thread) ---------------------
__global__ void k_setup(const float* __restrict__ pm) {
    if (threadIdx.x != 0 || blockIdx.x != 0) return;
    double fused[NV][16];
    for (int n = 0; n < NV; n++) {
        const float* p0 = pm + n * 32;
        const float* p1 = p0 + 16;
        for (int i = 0; i < 16; i++) fused[n][i] = (double)p0[i];
        for (int i = 0; i < 3; i++)
            for (int j = 0; j < 4; j++) {
                double s = 0.0;
                for (int k = 0; k < 3; k++) s += (double)p1[i*4+k] * (double)p0[k*4+j];
                fused[n][i*4+j] = s;
            }
    }
    double a[4][8];
    for (int i = 0; i < 4; i++)
        for (int j = 0; j < 4; j++) {
            a[i][j]   = fused[0][i*4+j];
            a[i][j+4] = (i == j) ? 1.0 : 0.0;
        }
    for (int col = 0; col < 4; col++) {
        int piv = col;
        for (int r = col + 1; r < 4; r++)
            if (fabs(a[r][col]) > fabs(a[piv][col])) piv = r;
        if (piv != col)
            for (int j = 0; j < 8; j++) { double t = a[col][j]; a[col][j] = a[piv][j]; a[piv][j] = t; }
        double d = a[col][col];
        for (int j = 0; j < 8; j++) a[col][j] /= d;
        for (int r = 0; r < 4; r++) {
            if (r == col) continue;
            double f = a[r][col];
            for (int j = 0; j < 8; j++) a[r][j] -= f * a[col][j];
        }
    }
    double inv[16];
    for (int i = 0; i < 4; i++)
        for (int j = 0; j < 4; j++) inv[i*4+j] = a[i][j+4];

    for (int v = 1; v < NV; v++) {
        double P[16];
        for (int i = 0; i < 4; i++)
            for (int j = 0; j < 4; j++) {
                double s = 0.0;
                for (int k = 0; k < 4; k++) s += fused[v][i*4+k] * inv[k*4+j];
                P[i*4+j] = s;
            }
        for (int i = 0; i < 3; i++)
            for (int j = 0; j < 3; j++) g_rot[v-1][i*3+j] = (float)P[i*4+j];
        for (int i = 0; i < 3; i++) g_trans[v-1][i] = (float)P[i*4+3];
    }
}

// ---------------- kernel 1: transpose features (N,C,H,W) -> (N,HW,C) --------
__global__ void k_transpose(const float* __restrict__ f) {
    __shared__ float tile[32][33];
    int n  = blockIdx.z;
    int p0 = blockIdx.x * 32;
    int tx = threadIdx.x, ty = threadIdx.y;
    tile[ty][tx] = f[((size_t)(n*CC + ty))*HWSZ + p0 + tx];
    __syncthreads();
    g_feaT[((size_t)(n*HWSZ + p0 + ty))*CC + tx] = tile[tx][ty];
}

// ---------------- kernel 2: warp + variance (planar output) -----------------
__global__ void __launch_bounds__(128) k_var(const float* __restrict__ dv) {
    __shared__ int4   s_idx[4][4][32];
    __shared__ float4 s_wt [4][4][32];
    __shared__ int    s_hw [4][32];
    __shared__ float  s_var[128*33];

    const int tid  = threadIdx.x;
    const int warp = tid >> 5;
    const int lane = tid & 31;
    const int gblock = blockIdx.x * 128;

    {
        int g  = gblock + tid;
        int d  = g / HWSZ;
        int hw = g - d * HWSZ;
        int h  = hw / WW;
        int w  = hw - h * WW;
        float fx = (float)w, fy = (float)h;
        float depth = __ldg(dv + d);
        #pragma unroll
        for (int v = 0; v < NS; v++) {
            float r0 = g_rot[v][0], r1 = g_rot[v][1], r2 = g_rot[v][2];
            float r3 = g_rot[v][3], r4 = g_rot[v][4], r5 = g_rot[v][5];
            float r6 = g_rot[v][6], r7 = g_rot[v][7], r8 = g_rot[v][8];
            float t0 = g_trans[v][0], t1 = g_trans[v][1], t2 = g_trans[v][2];
            float rx = r0*fx + r1*fy + r2;
            float ry = r3*fx + r4*fy + r5;
            float rz = r6*fx + r7*fy + r8;
            float X = rx*depth + t0;
            float Y = ry*depth + t1;
            float Z = rz*depth + t2;
            float px = X / Z;
            float py = Y / Z;
            float x0 = floorf(px), y0 = floorf(py);
            float x1 = x0 + 1.0f,  y1 = y0 + 1.0f;
            float wx1 = px - x0, wx0 = 1.0f - wx1;
            float wy1 = py - y0, wy0 = 1.0f - wy1;
            bool vx0 = (x0 >= 0.0f) && (x0 <= (float)(WW-1));
            bool vx1 = (x1 >= 0.0f) && (x1 <= (float)(WW-1));
            bool vy0 = (y0 >= 0.0f) && (y0 <= (float)(HH-1));
            bool vy1 = (y1 >= 0.0f) && (y1 <= (float)(HH-1));
            int cx0 = (int)fminf(fmaxf(x0, 0.0f), (float)(WW-1));
            int cx1 = (int)fminf(fmaxf(x1, 0.0f), (float)(WW-1));
            int cy0 = (int)fminf(fmaxf(y0, 0.0f), (float)(HH-1));
            int cy1 = (int)fminf(fmaxf(y1, 0.0f), (float)(HH-1));
            int4 id;
            id.x = cy0*WW + cx0;
            id.y = cy0*WW + cx1;
            id.z = cy1*WW + cx0;
            id.w = cy1*WW + cx1;
            float4 wt;
            wt.x = wx0*wy0 * ((vx0 && vy0) ? 1.0f : 0.0f);
            wt.y = wx1*wy0 * ((vx1 && vy0) ? 1.0f : 0.0f);
            wt.z = wx0*wy1 * ((vx0 && vy1) ? 1.0f : 0.0f);
            wt.w = wx1*wy1 * ((vx1 && vy1) ? 1.0f : 0.0f);
            s_idx[warp][v][lane] = id;
            s_wt [warp][v][lane] = wt;
        }
        s_hw[warp][lane] = hw;
    }
    __syncwarp();

    const int cg = lane & 7;
    const int q  = lane >> 3;
    const float4* fT = (const float4*)g_feaT;
    const float invN = 1.0f / (float)NV;

    #pragma unroll
    for (int it = 0; it < 8; it++) {
        int pt  = it*4 + q;
        int hw2 = s_hw[warp][pt];
        float4 ref = fT[hw2*8 + cg];
        float sx = ref.x, sy = ref.y, sz = ref.z, sw = ref.w;
        float qx = ref.x*ref.x, qy = ref.y*ref.y, qz = ref.z*ref.z, qw = ref.w*ref.w;
        #pragma unroll
        for (int v = 0; v < NS; v++) {
            int4   id = s_idx[warp][v][pt];
            float4 wt = s_wt [warp][v][pt];
            const float4* fv = fT + (size_t)(v+1)*HWSZ*8;
            float4 c00 = fv[id.x*8 + cg];
            float4 c01 = fv[id.y*8 + cg];
            float4 c10 = fv[id.z*8 + cg];
            float4 c11 = fv[id.w*8 + cg];
            float vx = wt.x*c00.x + wt.y*c01.x + wt.z*c10.x + wt.w*c11.x;
            float vy = wt.x*c00.y + wt.y*c01.y + wt.z*c10.y + wt.w*c11.y;
            float vz = wt.x*c00.z + wt.y*c01.z + wt.z*c10.z + wt.w*c11.z;
            float vw = wt.x*c00.w + wt.y*c01.w + wt.z*c10.w + wt.w*c11.w;
            sx += vx; sy += vy; sz += vz; sw += vw;
            qx += vx*vx; qy += vy*vy; qz += vz*vz; qw += vw*vw;
        }
        float mx = sx*invN, my = sy*invN, mz = sz*invN, mw = sw*invN;
        float vrx = qx*invN - mx*mx;
        float vry = qy*invN - my*my;
        float vrz = qz*invN - mz*mz;
        float vrw = qw*invN - mw*mw;
        int sbase = (warp*32 + pt)*33 + cg*4;
        s_var[sbase+0] = vrx;
        s_var[sbase+1] = vry;
        s_var[sbase+2] = vrz;
        s_var[sbase+3] = vrw;
    }
    __syncthreads();

    int gg = gblock + tid;
    #pragma unroll
    for (int c = 0; c < CC; c++)
        g_var[(size_t)c*DHWSZ + gg] = s_var[tid*33 + c];
}

// ---------------- kernel 3: 3x3x3 conv, 16 channels per block (z-split) -----
__global__ void __launch_bounds__(CONV_THREADS) k_conv(const float* __restrict__ wgt) {
    __shared__ float slab[HS][DS][WP];              // 40.3 KB, w-contiguous
    __shared__ unsigned long long wpk[CPB*27];      // 3.5 KB packed {k,k}

    const int tid = threadIdx.x;
    const int h0  = blockIdx.x * HT;
    const int d0  = blockIdx.y * DT;
    const int c0  = blockIdx.z * CPB;
    float* __restrict__ outbuf = blockIdx.z ? g_cost2 : g_cost;
    const int wg  = tid % 40;
    const int hl  = tid / 40;                       // 0..HT-1
    const int w0  = wg * 4;

    // prepack this block's weight pairs
    for (int i = tid; i < CPB*27; i += CONV_THREADS) {
        float k = __ldg(wgt + c0*27 + i);
        wpk[i] = pk2(k, k);
    }
    // zero halo columns (s=0..3 and s=164..167); only s=3 and s=164 are read
    for (int i = tid; i < HS*DS; i += CONV_THREADS) {
        int shy = i / DS, sdd = i % DS;
        float* row = &slab[shy][sdd][0];
        row[0] = 0.f; row[1] = 0.f; row[2] = 0.f; row[3] = 0.f;
        row[164] = 0.f; row[165] = 0.f; row[166] = 0.f; row[167] = 0.f;
    }

    // accumulators: A[od][0] = outputs (w0, w0+1), A[od][1] = (w0+2, w0+3)
    unsigned long long A[DT][2];
    #pragma unroll
    for (int od = 0; od < DT; od++) { A[od][0] = 0ull; A[od][1] = 0ull; }

    #pragma unroll 1
    for (int c = 0; c < CPB; c++) {
        __syncthreads();   // previous compute done / halo visible

        // ---- cooperative slab load: 60 rows x 160 w, float4, coalesced ----
        const float* __restrict__ vc = g_var + (size_t)(c0 + c) * DHWSZ;
        #pragma unroll
        for (int r = 0; r < 15; r++) {
            int idx = r*CONV_THREADS + tid;          // 0..2399
            int row = idx / 40;                      // 0..59
            int w4  = (idx % 40) * 4;
            int shy = row / DS;                      // 0..5
            int sdd = row - shy*DS;                  // 0..9
            int dd  = d0 - 1 + sdd;
            int hy  = h0 - 1 + shy;
            float4 v = make_float4(0.f, 0.f, 0.f, 0.f);
            if (dd >= 0 && dd < DDEP && hy >= 0 && hy < HH)
                v = *(const float4*)(vc + (size_t)dd*HWSZ + hy*WW + w4);
            *(float4*)&slab[shy][sdd][w4 + 4] = v;   // always store (zero if OOB)
        }
        __syncthreads();

        // ---- compute ----
        const unsigned long long* wc = wpk + c*27;   // [(dz*3+dy)*3+dx]
        #pragma unroll
        for (int dy = 0; dy < 3; dy++) {
            unsigned long long k00 = wc[(0*3+dy)*3+0], k01 = wc[(0*3+dy)*3+1], k02 = wc[(0*3+dy)*3+2];
            unsigned long long k10 = wc[(1*3+dy)*3+0], k11 = wc[(1*3+dy)*3+1], k12 = wc[(1*3+dy)*3+2];
            unsigned long long k20 = wc[(2*3+dy)*3+0], k21 = wc[(2*3+dy)*3+1], k22 = wc[(2*3+dy)*3+2];
            const float* hrow = &slab[hl + dy][0][0];
            #pragma unroll
            for (int sdd = 0; sdd < DS; sdd++) {
                const float* col = hrow + sdd*WP;
                float4 a = *(const float4*)(col + w0 + 4);   // w0..w0+3
                float2 l = *(const float2*)(col + w0 + 2);   // w0-2, w0-1
                float2 rr = *(const float2*)(col + w0 + 8);  // w0+4, w0+5
                unsigned long long P0 = pk2(l.y,  a.x);      // (v-1, v0)
                unsigned long long P1 = pk2(a.x,  a.y);      // (v0, v1)
                unsigned long long P2 = pk2(a.y,  a.z);      // (v1, v2)
                unsigned long long P3 = pk2(a.z,  a.w);      // (v2, v3)
                unsigned long long P4 = pk2(a.w,  rr.x);     // (v3, v4)
                #pragma unroll
                for (int dz = 0; dz < 3; dz++) {
                    int od = sdd - dz;
                    if (od < 0 || od >= DT) continue;        // compile-time resolved
                    unsigned long long q0 = (dz==0) ? k00 : (dz==1) ? k10 : k20;
                    unsigned long long q1 = (dz==0) ? k01 : (dz==1) ? k11 : k21;
                    unsigned long long q2 = (dz==0) ? k02 : (dz==1) ? k12 : k22;
                    A[od][0] = fma2(P0, q0, A[od][0]);
                    A[od][0] = fma2(P1, q1, A[od][0]);
                    A[od][0] = fma2(P2, q2, A[od][0]);
                    A[od][1] = fma2(P2, q0, A[od][1]);
                    A[od][1] = fma2(P3, q1, A[od][1]);
                    A[od][1] = fma2(P4, q2, A[od][1]);
                }
            }
        }
    }

    // ---- store 4w x 8d partial outputs ----
    const int ob = (h0 + hl)*WW + w0;
    #pragma unroll
    for (int od = 0; od < DT; od++) {
        float o0, o1, o2, o3;
        upk2(A[od][0], o0, o1);
        upk2(A[od][1], o2, o3);
        float4 v = make_float4(o0, o1, o2, o3);
        *(float4*)(outbuf + (size_t)(d0 + od)*HWSZ + ob) = v;
    }
}

// ---------------- kernel 4: softmax / depth / confidence --------------------
__global__ void __launch_bounds__(256) k_post(const float* __restrict__ dv,
                                              float* __restrict__ out) {
    int pix = blockIdx.x * 256 + threadIdx.x;
    float p[DDEP];
    float mx = -1e30f;
    #pragma unroll
    for (int d = 0; d < DDEP; d++) {
        p[d] = g_cost[(size_t)d*HWSZ + pix] + g_cost2[(size_t)d*HWSZ + pix];
        mx = fmaxf(mx, p[d]);
    }
    float s = 0.0f;
    #pragma unroll
    for (int d = 0; d < DDEP; d++) { p[d] = expf(p[d] - mx); s += p[d]; }
    float inv = 1.0f / s;
    float depth = 0.0f, didx = 0.0f;
    #pragma unroll
    for (int d = 0; d < DDEP; d++) {
        float pr = p[d] * inv;
        p[d] = pr;
        depth += pr * __ldg(dv + d);
        didx  += pr * (float)d;
    }
    int di = (int)didx;
    di = min(max(di, 0), DDEP - 1);
    float conf = 0.0f;
    #pragma unroll
    for (int d = 0; d < DDEP; d++) {
        bool inwin = (d >= di - 1) && (d <= di + 2);
        conf += inwin ? p[d] : 0.0f;
    }
    out[pix]        = depth;
    out[HWSZ + pix] = conf;
}

// ---------------- launcher ---------------------------------------------------
extern "C" void kernel_launch(void* const* d_in, const int* in_sizes, int n_in,
                              void* d_out, int out_size) {
    const float* features = nullptr;
    const float* pm       = nullptr;
    const float* dv       = nullptr;
    const float* wgt      = nullptr;
    for (int i = 0; i < n_in; i++) {
        switch (in_sizes[i]) {
            case NV*CC*HWSZ: features = (const float*)d_in[i]; break;
            case 160:        pm       = (const float*)d_in[i]; break;
            case 48:         dv       = (const float*)d_in[i]; break;
            case 864:        wgt      = (const float*)d_in[i]; break;
            default: break;
        }
    }
    if (!features) features = (const float*)d_in[0];
    if (!pm)       pm       = (const float*)d_in[1];
    if (!dv)       dv       = (const float*)d_in[2];
    if (!wgt)      wgt      = (const float*)d_in[3];
    float* out = (float*)d_out;

    k_setup<<<1, 32>>>(pm);
    k_transpose<<<dim3(HWSZ/32, 1, NV), dim3(32, 32)>>>(features);
    k_var<<<DHWSZ/128, 128>>>(dv);
    k_conv<<<dim3(HH/HT, DDEP/DT, CSPLIT), CONV_THREADS>>>(wgt);
    k_post<<<HWSZ/256, 256>>>(dv, out);
}